// round 11
// baseline (speedup 1.0000x reference)
#include <cuda_runtime.h>
#include <math.h>

// Problem shape (fixed by the dataset).
#define BATCH 1024
#define NBG   256
#define DIM   512
#define DIM4  (DIM/4)              // 128 float4 per row

#define ROWS_PER_WARP   8
#define WARPS_PER_BLOCK 8
#define THREADS_PER_BLOCK (WARPS_PER_BLOCK*32)
#define ROWS_PER_BLOCK  (ROWS_PER_WARP*WARPS_PER_BLOCK)   // 64
#define BG_BLOCKS ((BATCH*NBG)/ROWS_PER_BLOCK)            // 4096
#define MIN_BLOCKS_PER_SM 5                               // cap regs at 48

// Deterministic partial sums (no atomics in the summation -> bitwise
// identical every replay; the atomic below only ELECTS the reducing block).
__device__ float g_partial_bg[BG_BLOCKS];
__device__ float g_partial_pos[BATCH];
__device__ unsigned int g_done_count;   // zero-init; reset by elected block each launch

__device__ __forceinline__ float warp_sum(float v) {
    #pragma unroll
    for (int o = 16; o > 0; o >>= 1)
        v += __shfl_xor_sync(0xFFFFFFFFu, v, o);
    return v;
}

// 256-bit streaming global load (sm_100+/PTX 8.8). One warp-wide issue = 1 KB,
// evict-first so the 512 MB read-once stream doesn't displace img rows in L2.
__device__ __forceinline__ void ldg256_cs(const float* p,
                                          float& r0, float& r1, float& r2, float& r3,
                                          float& r4, float& r5, float& r6, float& r7) {
    asm volatile("ld.global.cs.v8.f32 {%0,%1,%2,%3,%4,%5,%6,%7}, [%8];"
                 : "=f"(r0), "=f"(r1), "=f"(r2), "=f"(r3),
                   "=f"(r4), "=f"(r5), "=f"(r6), "=f"(r7)
                 : "l"(p));
}

// ---------------------------------------------------------------------------
// Fused single-kernel InfoNCE loss. bg streamed with LDG.256.cs. Positive
// logit hoisted BEFORE the stream loop so its registers die early, giving
// ptxas the full 48-reg budget for load batching in the hot loop. Lane
// mapping: lane owns elements [lane*8, lane*8+8) and [256+lane*8, +8);
// the warp reductions are mapping-agnostic.
// ---------------------------------------------------------------------------
__global__ void __launch_bounds__(THREADS_PER_BLOCK, MIN_BLOCKS_PER_SM)
bg_kernel(const float* __restrict__ img, const float* __restrict__ fg,
          const float* __restrict__ bg, float* __restrict__ out)
{
    const int warp = threadIdx.x >> 5;
    const int lane = threadIdx.x & 31;
    const int rowBase = blockIdx.x * ROWS_PER_BLOCK + warp * ROWS_PER_WARP;
    const int b = blockIdx.x >> 2;   // 4 blocks per batch row; 64 rows/block in one b

    // img row in registers, in the v8 lane mapping (float4 idx lane*2 (+1), +64).
    const float4* irow = reinterpret_cast<const float4*>(img + (size_t)b * DIM);
    float iv0[8], iv1[8];
    {
        float4 a0 = irow[lane*2],      a1 = irow[lane*2 + 1];
        float4 b0 = irow[lane*2 + 64], b1 = irow[lane*2 + 65];
        iv0[0]=a0.x; iv0[1]=a0.y; iv0[2]=a0.z; iv0[3]=a0.w;
        iv0[4]=a1.x; iv0[5]=a1.y; iv0[6]=a1.z; iv0[7]=a1.w;
        iv1[0]=b0.x; iv1[1]=b0.y; iv1[2]=b0.z; iv1[3]=b0.w;
        iv1[4]=b1.x; iv1[5]=b1.y; iv1[6]=b1.z; iv1[7]=b1.w;
    }
    float nrm = 0.f;
    #pragma unroll
    for (int j = 0; j < 8; j++) nrm += iv0[j]*iv0[j] + iv1[j]*iv1[j];
    nrm = warp_sum(nrm);
    const float rinv = rsqrtf(nrm);

    // Positive logit for batch b (warp 0 of the first block of each b),
    // done up-front so its registers die before the streaming loop.
    if (((blockIdx.x & 3) == 0) && warp == 0) {
        const float4* frow = reinterpret_cast<const float4*>(fg + (size_t)b * DIM);
        float4 a0 = frow[lane*2],      a1 = frow[lane*2 + 1];
        float4 b0 = frow[lane*2 + 64], b1 = frow[lane*2 + 65];
        float dp = a0.x*iv0[0] + a0.y*iv0[1] + a0.z*iv0[2] + a0.w*iv0[3]
                 + a1.x*iv0[4] + a1.y*iv0[5] + a1.z*iv0[6] + a1.w*iv0[7]
                 + b0.x*iv1[0] + b0.y*iv1[1] + b0.z*iv1[2] + b0.w*iv1[3]
                 + b1.x*iv1[4] + b1.y*iv1[5] + b1.z*iv1[6] + b1.w*iv1[7];
        dp = warp_sum(dp);
        if (lane == 0) g_partial_pos[b] = __expf(dp * rinv);
    }

    const float* rowp = bg + (size_t)rowBase * DIM;

    // Per-lane partial dot for each of the 8 rows: 2 x LDG.256.cs per row.
    float d[ROWS_PER_WARP];
    #pragma unroll
    for (int r = 0; r < ROWS_PER_WARP; r++) {
        const float* row = rowp + (size_t)r * DIM;
        float x0,x1,x2,x3,x4,x5,x6,x7;
        float y0,y1,y2,y3,y4,y5,y6,y7;
        ldg256_cs(row + lane*8,        x0,x1,x2,x3,x4,x5,x6,x7);
        ldg256_cs(row + 256 + lane*8,  y0,y1,y2,y3,y4,y5,y6,y7);
        float a0 = x0*iv0[0] + x1*iv0[1] + x2*iv0[2] + x3*iv0[3]
                 + x4*iv0[4] + x5*iv0[5] + x6*iv0[6] + x7*iv0[7];
        a0 += y0*iv1[0] + y1*iv1[1] + y2*iv1[2] + y3*iv1[3]
            + y4*iv1[4] + y5*iv1[5] + y6*iv1[6] + y7*iv1[7];
        d[r] = a0;
    }

    // Folded butterfly: reduce 8 row-dots across 32 lanes in 9 shuffles.
    #pragma unroll
    for (int i = 0; i < 4; i++) {
        float a  = (lane & 16) ? d[i+4] : d[i];
        float bv = (lane & 16) ? d[i]   : d[i+4];
        d[i] = a + __shfl_xor_sync(0xFFFFFFFFu, bv, 16);
    }
    #pragma unroll
    for (int i = 0; i < 2; i++) {
        float a  = (lane & 8) ? d[i+2] : d[i];
        float bv = (lane & 8) ? d[i]   : d[i+2];
        d[i] = a + __shfl_xor_sync(0xFFFFFFFFu, bv, 8);
    }
    float v;
    {
        float a  = (lane & 4) ? d[1] : d[0];
        float bv = (lane & 4) ? d[0] : d[1];
        v = a + __shfl_xor_sync(0xFFFFFFFFu, bv, 4);
    }
    v += __shfl_xor_sync(0xFFFFFFFFu, v, 2);
    v += __shfl_xor_sync(0xFFFFFFFFu, v, 1);
    float e = __expf(v * rinv);
    float acc = ((lane & 3) == 0) ? e : 0.f;

    // Block reduction of the 8 masked exps per warp.
    acc = warp_sum(acc);
    __shared__ float s[WARPS_PER_BLOCK];
    __shared__ bool s_last;
    if (lane == 0) s[warp] = acc;
    __syncthreads();
    if (threadIdx.x == 0) {
        float t = 0.f;
        #pragma unroll
        for (int w = 0; w < WARPS_PER_BLOCK; w++) t += s[w];
        g_partial_bg[blockIdx.x] = t;
        __threadfence();
        unsigned int c = atomicAdd(&g_done_count, 1u);
        s_last = (c == (unsigned int)(BG_BLOCKS - 1));
    }
    __syncthreads();

    // Last-to-finish block performs the final deterministic reduction.
    if (s_last) {
        const int t = threadIdx.x;
        const float4* pbg  = reinterpret_cast<const float4*>(g_partial_bg);
        const float4* ppos = reinterpret_cast<const float4*>(g_partial_pos);
        float a = 0.f;
        #pragma unroll
        for (int i = 0; i < BG_BLOCKS/4/THREADS_PER_BLOCK; i++) {   // 4 iters
            float4 x = pbg[t + i*THREADS_PER_BLOCK];
            a += x.x + x.y + x.z + x.w;
        }
        float p = 0.f;
        if (t < BATCH/4) {                                           // 256 lanes
            float4 x = ppos[t];
            p = x.x + x.y + x.z + x.w;
        }
        a = warp_sum(a);
        p = warp_sum(p);
        __shared__ float sb[WARPS_PER_BLOCK], sp[WARPS_PER_BLOCK];
        if (lane == 0) { sb[warp] = a; sp[warp] = p; }
        __syncthreads();
        if (threadIdx.x == 0) {
            float bgsum = 0.f, possum = 0.f;
            #pragma unroll
            for (int w = 0; w < WARPS_PER_BLOCK; w++) { bgsum += sb[w]; possum += sp[w]; }
            out[0] = log1pf(bgsum / possum);
            g_done_count = 0;   // reset for next graph replay
        }
    }
}

extern "C" void kernel_launch(void* const* d_in, const int* in_sizes, int n_in,
                              void* d_out, int out_size)
{
    const float* fg_img = (const float*)d_in[0];   // [B, D]
    const float* fg_pro = (const float*)d_in[1];   // [B, D]
    const float* bg_pro = (const float*)d_in[2];   // [B, N, D]
    float* out = (float*)d_out;

    bg_kernel<<<BG_BLOCKS, THREADS_PER_BLOCK>>>(fg_img, fg_pro, bg_pro, out);
}

// round 12
// speedup vs baseline: 1.0153x; 1.0153x over previous
#include <cuda_runtime.h>
#include <math.h>

// Problem shape (fixed by the dataset).
#define BATCH 1024
#define NBG   256
#define DIM   512
#define DIM4  (DIM/4)              // 128 float4 per row

#define ROWS_PER_WARP   8
#define WARPS_PER_BLOCK 8
#define THREADS_PER_BLOCK (WARPS_PER_BLOCK*32)
#define ROWS_PER_BLOCK  (ROWS_PER_WARP*WARPS_PER_BLOCK)   // 64
#define BG_BLOCKS ((BATCH*NBG)/ROWS_PER_BLOCK)            // 4096
#define MIN_BLOCKS_PER_SM 5                               // cap regs at 48

// Deterministic partial sums (no atomics in the summation -> bitwise
// identical every replay; the atomic below only ELECTS the reducing block).
__device__ float g_partial_bg[BG_BLOCKS];
__device__ float g_partial_pos[BATCH];
__device__ unsigned int g_done_count;   // zero-init; reset by elected block each launch

__device__ __forceinline__ float warp_sum(float v) {
    #pragma unroll
    for (int o = 16; o > 0; o >>= 1)
        v += __shfl_xor_sync(0xFFFFFFFFu, v, o);
    return v;
}

// 256-bit streaming global load (sm_100+/PTX 8.8). One warp-wide issue = 1 KB,
// evict-first so the 512 MB read-once stream doesn't displace img rows in L2.
__device__ __forceinline__ void ldg256_cs(const float* p,
                                          float& r0, float& r1, float& r2, float& r3,
                                          float& r4, float& r5, float& r6, float& r7) {
    asm volatile("ld.global.cs.v8.f32 {%0,%1,%2,%3,%4,%5,%6,%7}, [%8];"
                 : "=f"(r0), "=f"(r1), "=f"(r2), "=f"(r3),
                   "=f"(r4), "=f"(r5), "=f"(r6), "=f"(r7)
                 : "l"(p));
}

// ---------------------------------------------------------------------------
// Fused single-kernel InfoNCE loss — final configuration (measured best).
// Streams bg (512 MB read-once) with LDG.256.cs at the B300 LTS data-return
// cap (~6.4 TB/s measured, invariant across occupancy/grid/width/policy),
// folded-butterfly warp reduction (9 shuffles / 8 rows), positive logit in
// warp 0 of every 4th block, final loss in the last-to-finish block
// (atomic elects the reducer; summation order is fixed and deterministic).
// Lane mapping: lane owns elements [lane*8, lane*8+8) and [256+lane*8, +8).
// ---------------------------------------------------------------------------
__global__ void __launch_bounds__(THREADS_PER_BLOCK, MIN_BLOCKS_PER_SM)
bg_kernel(const float* __restrict__ img, const float* __restrict__ fg,
          const float* __restrict__ bg, float* __restrict__ out)
{
    const int warp = threadIdx.x >> 5;
    const int lane = threadIdx.x & 31;
    const int rowBase = blockIdx.x * ROWS_PER_BLOCK + warp * ROWS_PER_WARP;
    const int b = blockIdx.x >> 2;   // 4 blocks per batch row; 64 rows/block in one b

    // img row in registers, in the v8 lane mapping (float4 idx lane*2 (+1), +64).
    const float4* irow = reinterpret_cast<const float4*>(img + (size_t)b * DIM);
    float iv0[8], iv1[8];
    {
        float4 a0 = irow[lane*2],      a1 = irow[lane*2 + 1];
        float4 b0 = irow[lane*2 + 64], b1 = irow[lane*2 + 65];
        iv0[0]=a0.x; iv0[1]=a0.y; iv0[2]=a0.z; iv0[3]=a0.w;
        iv0[4]=a1.x; iv0[5]=a1.y; iv0[6]=a1.z; iv0[7]=a1.w;
        iv1[0]=b0.x; iv1[1]=b0.y; iv1[2]=b0.z; iv1[3]=b0.w;
        iv1[4]=b1.x; iv1[5]=b1.y; iv1[6]=b1.z; iv1[7]=b1.w;
    }
    float nrm = 0.f;
    #pragma unroll
    for (int j = 0; j < 8; j++) nrm += iv0[j]*iv0[j] + iv1[j]*iv1[j];
    nrm = warp_sum(nrm);
    const float rinv = rsqrtf(nrm);

    const float* rowp = bg + (size_t)rowBase * DIM;

    // Per-lane partial dot for each of the 8 rows: 2 x LDG.256.cs per row.
    float d[ROWS_PER_WARP];
    #pragma unroll
    for (int r = 0; r < ROWS_PER_WARP; r++) {
        const float* row = rowp + (size_t)r * DIM;
        float x0,x1,x2,x3,x4,x5,x6,x7;
        float y0,y1,y2,y3,y4,y5,y6,y7;
        ldg256_cs(row + lane*8,        x0,x1,x2,x3,x4,x5,x6,x7);
        ldg256_cs(row + 256 + lane*8,  y0,y1,y2,y3,y4,y5,y6,y7);
        float a0 = x0*iv0[0] + x1*iv0[1] + x2*iv0[2] + x3*iv0[3]
                 + x4*iv0[4] + x5*iv0[5] + x6*iv0[6] + x7*iv0[7];
        a0 += y0*iv1[0] + y1*iv1[1] + y2*iv1[2] + y3*iv1[3]
            + y4*iv1[4] + y5*iv1[5] + y6*iv1[6] + y7*iv1[7];
        d[r] = a0;
    }

    // Folded butterfly: reduce 8 row-dots across 32 lanes in 9 shuffles.
    #pragma unroll
    for (int i = 0; i < 4; i++) {
        float a  = (lane & 16) ? d[i+4] : d[i];
        float bv = (lane & 16) ? d[i]   : d[i+4];
        d[i] = a + __shfl_xor_sync(0xFFFFFFFFu, bv, 16);
    }
    #pragma unroll
    for (int i = 0; i < 2; i++) {
        float a  = (lane & 8) ? d[i+2] : d[i];
        float bv = (lane & 8) ? d[i]   : d[i+2];
        d[i] = a + __shfl_xor_sync(0xFFFFFFFFu, bv, 8);
    }
    float v;
    {
        float a  = (lane & 4) ? d[1] : d[0];
        float bv = (lane & 4) ? d[0] : d[1];
        v = a + __shfl_xor_sync(0xFFFFFFFFu, bv, 4);
    }
    v += __shfl_xor_sync(0xFFFFFFFFu, v, 2);
    v += __shfl_xor_sync(0xFFFFFFFFu, v, 1);
    float e = __expf(v * rinv);
    float acc = ((lane & 3) == 0) ? e : 0.f;

    // Positive logit for batch b: warp 0 of the first block of each b
    // (same v8 lane mapping as iv).
    if (((blockIdx.x & 3) == 0) && warp == 0) {
        const float4* frow = reinterpret_cast<const float4*>(fg + (size_t)b * DIM);
        float4 a0 = frow[lane*2],      a1 = frow[lane*2 + 1];
        float4 b0 = frow[lane*2 + 64], b1 = frow[lane*2 + 65];
        float dp = a0.x*iv0[0] + a0.y*iv0[1] + a0.z*iv0[2] + a0.w*iv0[3]
                 + a1.x*iv0[4] + a1.y*iv0[5] + a1.z*iv0[6] + a1.w*iv0[7]
                 + b0.x*iv1[0] + b0.y*iv1[1] + b0.z*iv1[2] + b0.w*iv1[3]
                 + b1.x*iv1[4] + b1.y*iv1[5] + b1.z*iv1[6] + b1.w*iv1[7];
        dp = warp_sum(dp);
        if (lane == 0) g_partial_pos[b] = __expf(dp * rinv);
    }

    // Block reduction of the 8 masked exps per warp.
    acc = warp_sum(acc);
    __shared__ float s[WARPS_PER_BLOCK];
    __shared__ bool s_last;
    if (lane == 0) s[warp] = acc;
    __syncthreads();
    if (threadIdx.x == 0) {
        float t = 0.f;
        #pragma unroll
        for (int w = 0; w < WARPS_PER_BLOCK; w++) t += s[w];
        g_partial_bg[blockIdx.x] = t;
        __threadfence();
        unsigned int c = atomicAdd(&g_done_count, 1u);
        s_last = (c == (unsigned int)(BG_BLOCKS - 1));
    }
    __syncthreads();

    // Last-to-finish block performs the final deterministic reduction.
    if (s_last) {
        const int t = threadIdx.x;
        const float4* pbg  = reinterpret_cast<const float4*>(g_partial_bg);
        const float4* ppos = reinterpret_cast<const float4*>(g_partial_pos);
        float a = 0.f;
        #pragma unroll
        for (int i = 0; i < BG_BLOCKS/4/THREADS_PER_BLOCK; i++) {   // 4 iters
            float4 x = pbg[t + i*THREADS_PER_BLOCK];
            a += x.x + x.y + x.z + x.w;
        }
        float p = 0.f;
        if (t < BATCH/4) {                                           // 256 lanes
            float4 x = ppos[t];
            p = x.x + x.y + x.z + x.w;
        }
        a = warp_sum(a);
        p = warp_sum(p);
        __shared__ float sb[WARPS_PER_BLOCK], sp[WARPS_PER_BLOCK];
        if (lane == 0) { sb[warp] = a; sp[warp] = p; }
        __syncthreads();
        if (threadIdx.x == 0) {
            float bgsum = 0.f, possum = 0.f;
            #pragma unroll
            for (int w = 0; w < WARPS_PER_BLOCK; w++) { bgsum += sb[w]; possum += sp[w]; }
            out[0] = log1pf(bgsum / possum);
            g_done_count = 0;   // reset for next graph replay
        }
    }
}

extern "C" void kernel_launch(void* const* d_in, const int* in_sizes, int n_in,
                              void* d_out, int out_size)
{
    const float* fg_img = (const float*)d_in[0];   // [B, D]
    const float* fg_pro = (const float*)d_in[1];   // [B, D]
    const float* bg_pro = (const float*)d_in[2];   // [B, N, D]
    float* out = (float*)d_out;

    bg_kernel<<<BG_BLOCKS, THREADS_PER_BLOCK>>>(fg_img, fg_pro, bg_pro, out);
}